// round 8
// baseline (speedup 1.0000x reference)
#include <cuda_runtime.h>

#define TT   1000
#define HH   4096
#define PP   16
#define NCTA 8           // one cluster of 8 CTAs
#define TPB  128         // 4 warps; 4 neurons/thread: 8*128*4 = 4096
#define NW   (TPB / 32)
#define NN   4           // neurons per thread
#define NPROD (NCTA * NW)   // 32 producer warps

// Scratch (device globals; no allocation). Rewritten identically every replay.
__device__ float g_pre[TT * HH];   // Win@x + noise/10
__device__ float g_r[TT * HH];     // r_t[h] trace (consumed by y_kernel)

// ---- PTX helpers ------------------------------------------------------------
__device__ __forceinline__ unsigned smem_u32(const void* p) {
    return (unsigned)__cvta_generic_to_shared(p);
}
__device__ __forceinline__ unsigned mapa_sh(unsigned local, unsigned rank) {
    unsigned r;
    asm volatile("mapa.shared::cluster.u32 %0, %1, %2;" : "=r"(r) : "r"(local), "r"(rank));
    return r;
}
__device__ __forceinline__ void st_cluster_f32(unsigned addr, float v) {
    asm volatile("st.shared::cluster.f32 [%0], %1;" :: "r"(addr), "f"(v) : "memory");
}
__device__ __forceinline__ void st_rel_cluster_u32(unsigned addr, unsigned v) {
    asm volatile("st.release.cluster.shared::cluster.u32 [%0], %1;"
                 :: "r"(addr), "r"(v) : "memory");
}
__device__ __forceinline__ unsigned ld_acq_cluster(unsigned addr) {
    unsigned v;
    asm volatile("ld.acquire.cluster.shared::cta.u32 %0, [%1];"
                 : "=r"(v) : "r"(addr) : "memory");
    return v;
}
__device__ __forceinline__ void cluster_sync() {
    asm volatile("barrier.cluster.arrive.aligned;" ::: "memory");
    asm volatile("barrier.cluster.wait.aligned;" ::: "memory");
}
__device__ __forceinline__ unsigned ctarank() {
    unsigned r; asm("mov.u32 %0, %%cluster_ctarank;" : "=r"(r)); return r;
}

// Fold 16 per-lane values across the warp: 16 shuffles, 5 dependent levels.
// Returns the full warp-sum of value index ((lane>>1)&15) — duplicated in
// each even/odd lane pair.
__device__ __forceinline__ float fold16(float v[PP], int lane) {
#pragma unroll
    for (int m = 16; m >= 2; m >>= 1) {
        const int off = m >> 1;
        const bool hi = (lane & m) != 0;
#pragma unroll
        for (int i = 0; i < off; i++) {
            float keep = hi ? v[i + off] : v[i];
            float send = hi ? v[i] : v[i + off];
            float recv = __shfl_xor_sync(0xffffffffu, send, m);
            v[i] = keep + recv;
        }
    }
    return v[0] + __shfl_xor_sync(0xffffffffu, v[0], 1);
}

// pre[t][h] = Win[h,:]@x[t,:] + noise[t,h]/10
__global__ void pre_kernel(const float* __restrict__ noise,
                           const float* __restrict__ x,
                           const float* __restrict__ Win)
{
    int i = blockIdx.x * blockDim.x + threadIdx.x;
    if (i < TT * HH) {
        int t = i / HH, h = i - t * HH;
        float acc = noise[i] * 0.1f;
        const float* wr = &Win[h * 6];
        const float* xr = &x[t * 6];
#pragma unroll
        for (int k = 0; k < 6; k++) acc += wr[k] * xr[k];
        g_pre[i] = acc;
    }
}

// Shared layout (fixed offsets so peer addresses = peer_base + same offset).
struct alignas(128) ShMsg {
    float    msg[2][NPROD][17];   // stride 17: conflict-free gather
    unsigned flg[2][NPROD];       // monotonic tags (per producer warp)
};

__global__ void __launch_bounds__(TPB, 1) __cluster_dims__(NCTA, 1, 1)
snn_scan(const float* __restrict__ pin,    // [H,16]
         const float* __restrict__ pout,   // [H,16]
         const float* __restrict__ l,      // [16]
         const float* __restrict__ stau)   // [H]
{
    const int tid  = threadIdx.x;
    const int lane = tid & 31;
    const int warp = tid >> 5;
    const unsigned rank = ctarank();
    const int g = (int)rank * NW + warp;        // producer id 0..31

    __shared__ ShMsg sh;

    // zero flags (smem is fresh every launch)
    if (tid < 2 * NPROD) ((unsigned*)sh.flg)[tid] = 0u;
    __syncthreads();
    cluster_sync();   // zero-init visible before any remote store

    const unsigned base_local = smem_u32(&sh);
    // peer smem base addresses (same offsets valid within each peer's window)
    unsigned pb[NCTA];
#pragma unroll
    for (int c = 0; c < NCTA; c++) pb[c] = mapa_sh(base_local, (unsigned)c);

    const unsigned MSG0 = 0u;                                   // offsetof msg
    const unsigned FLG0 = (unsigned)(2 * NPROD * 17 * 4);       // offsetof flg

    // ---- per-neuron constants (x4) in registers ----
    const float drc    = 0.08208499862389880f;   // exp(-DT/TAU_R)
    const float c005dr = 0.005f * drc;

    int hh[NN];
    float dd[NN], sg[NN], ic[NN];
    float lp[NN][PP], kA[NN][PP];
#pragma unroll
    for (int k = 0; k < NN; k++) {
        hh[k] = (int)rank * TPB + tid + k * (NCTA * TPB);
        const float tau = 1.0f / (1.0f + expf(-stau[hh[k]])) * 0.03f + 0.02f;
        dd[k] = expf(-0.005f / tau);
        sg[k] = 2.5f / tau;                 // DT/(tau*TAU_R)
        ic[k] = tau * 80.0f;                // 1/(DT*sg)
#pragma unroll
        for (int p = 0; p < PP; p++) {
            lp[k][p] = l[p] * pin[hh[k] * PP + p];
            kA[k][p] = pout[hh[k] * PP + p] * (0.0125f / tau);   // po*DT*sg
        }
    }

    float mem[NN], rr[NN], ss[NN], pre[NN];
#pragma unroll
    for (int k = 0; k < NN; k++) {
        mem[k] = 0.f; rr[k] = 0.f; ss[k] = 0.f;
        pre[k] = g_pre[hh[k]];    // t = 0
    }
    float foldedB = 0.f;          // fold16 of decay-part contribution (B_0 = 0)

    const unsigned flg_local = base_local + FLG0;

    for (int t = 0; t < TT; t++) {
        // ============ consume: q = pout^T r_{t-1} (sum 32 msgs) ============
        float q = 0.f;
        if (t > 0) {
            const int sl = (t - 1) & 1;
            const unsigned fa = flg_local + (unsigned)(sl * NPROD + lane) * 4u;
            while (ld_acq_cluster(fa) != (unsigned)t) {}
            __syncwarp();
            // lane handles p=lane&15, producers g0..g0+15 (g0 = 16*(lane>>4))
            const float* m = &sh.msg[sl][(lane >> 4) * 16][lane & 15];
            float a[16];
#pragma unroll
            for (int j = 0; j < 16; j++) a[j] = m[j * 17];
            float s0 = ((a[0] + a[1]) + (a[2] + a[3])) + ((a[4] + a[5]) + (a[6] + a[7]));
            float s1 = ((a[8] + a[9]) + (a[10] + a[11])) + ((a[12] + a[13]) + (a[14] + a[15]));
            float sum = s0 + s1;
            q = sum + __shfl_xor_sync(0xffffffffu, sum, 16);  // all lanes: q[lane&15]
        }

        // ============ I and membrane update (4 neurons) ====================
        float acc0[NN], acc1[NN];
#pragma unroll
        for (int k = 0; k < NN; k++) { acc0[k] = pre[k]; acc1[k] = 0.f; }
#pragma unroll
        for (int p = 0; p < 8; p++) {
            const float qa = __shfl_sync(0xffffffffu, q, p);
            const float qb = __shfl_sync(0xffffffffu, q, p + 8);
#pragma unroll
            for (int k = 0; k < NN; k++) {
                acc0[k] += lp[k][p] * qa;
                acc1[k] += lp[k][p + 8] * qb;
            }
        }
        float f[NN];
#pragma unroll
        for (int k = 0; k < NN; k++) {
            mem[k] = 0.9f * mem[k] + (acc0[k] + acc1[k])
                   - ((mem[k] > 0.5f) ? 0.5f : 0.0f);
            f[k]   = (mem[k] > 0.5f) ? 1.0f : 0.0f;
        }

        // ============ spike part fold + direct per-warp publish ============
        float v[PP];
#pragma unroll
        for (int p = 0; p < PP; p++)
            v[p] = (f[0] * kA[0][p] + f[1] * kA[1][p])
                 + (f[2] * kA[2][p] + f[3] * kA[3][p]);
        const float vm = fold16(v, lane) + foldedB;   // M_t[(lane>>1)&15]

        const int sl2 = t & 1;
        const unsigned moff = MSG0
            + (unsigned)((sl2 * NPROD + g) * 17 + ((lane >> 1) & 15)) * 4u;
        if ((lane & 1) == 0) {
#pragma unroll
            for (int c = 0; c < NCTA; c++)
                st_cluster_f32(pb[c] + moff, vm);
        }
        __syncwarp();   // all lanes' data stores before the flag stores
        if (lane < NCTA) {
            const unsigned foff = FLG0 + (unsigned)(sl2 * NPROD + g) * 4u;
            st_rel_cluster_u32(pb[lane] + foff, (unsigned)(t + 1));
        }

        // ============ slack: state update, traces, next-step decay fold ====
        const int tn = (t + 1 < TT) ? (t + 1) : t;
        float rbn[NN];
#pragma unroll
        for (int k = 0; k < NN; k++) {
            ss[k] = ss[k] * drc + f[k] * sg[k];
            rr[k] = dd[k] * rr[k] + 0.005f * ss[k];
            g_r[t * HH + hh[k]] = rr[k];
            pre[k] = g_pre[tn * HH + hh[k]];
            rbn[k] = (dd[k] * rr[k] + c005dr * ss[k]) * ic[k];  // rbar_{t+1}/(DT*sg)
        }
        float vb[PP];
#pragma unroll
        for (int p = 0; p < PP; p++)
            vb[p] = (rbn[0] * kA[0][p] + rbn[1] * kA[1][p])
                  + (rbn[2] * kA[2][p] + rbn[3] * kA[3][p]);
        foldedB = fold16(vb, lane);
    }

    // No CTA may exit while peers' remote stores are in flight.
    cluster_sync();
}

// y[t,o] = Wout[o,:] @ r[t,:]  — one block per timestep, deterministic order.
__global__ void __launch_bounds__(256) y_kernel(const float* __restrict__ Wout,
                                                float* __restrict__ out)
{
    const int t   = blockIdx.x;
    const int tid = threadIdx.x;
    const int lane = tid & 31, warp = tid >> 5;
    float y0 = 0.f, y1 = 0.f;
#pragma unroll
    for (int j = 0; j < HH / 256; j++) {
        const int h  = tid + j * 256;
        const float rv = g_r[t * HH + h];
        y0 += Wout[h] * rv;
        y1 += Wout[HH + h] * rv;
    }
#pragma unroll
    for (int o = 16; o > 0; o >>= 1) {
        y0 += __shfl_xor_sync(0xffffffffu, y0, o);
        y1 += __shfl_xor_sync(0xffffffffu, y1, o);
    }
    __shared__ float s0[8], s1[8];
    if (lane == 0) { s0[warp] = y0; s1[warp] = y1; }
    __syncthreads();
    if (tid == 0) {
        float a0 = 0.f, a1 = 0.f;
#pragma unroll
        for (int w = 0; w < 8; w++) { a0 += s0[w]; a1 += s1[w]; }
        out[t * 2 + 0] = a0;
        out[t * 2 + 1] = a1;
    }
}

extern "C" void kernel_launch(void* const* d_in, const int* in_sizes, int n_in,
                              void* d_out, int out_size)
{
    const float* x     = (const float*)d_in[0];
    const float* noise = (const float*)d_in[1];
    const float* Win   = (const float*)d_in[2];
    const float* Wout  = (const float*)d_in[3];
    const float* pin   = (const float*)d_in[4];
    const float* pout  = (const float*)d_in[5];
    const float* l     = (const float*)d_in[6];
    const float* stau  = (const float*)d_in[7];
    float* out = (float*)d_out;

    pre_kernel<<<(TT * HH + 255) / 256, 256>>>(noise, x, Win);
    snn_scan<<<NCTA, TPB>>>(pin, pout, l, stau);
    y_kernel<<<TT, 256>>>(Wout, out);
}